// round 1
// baseline (speedup 1.0000x reference)
#include <cuda_runtime.h>
#include <cuda_bf16.h>
#include <cstdint>

#define NIMG 16
#define NBOX 16128
#define NCH  85
#define KSEL 500
#define KPAD 512
#define NJB  63            // ceil(500/8)
#define SIG_NEG4 0.017986210f   // sigmoid(-4) for zero-overlap pairs

// ---------------- device scratch (no allocations allowed) ----------------
__device__ unsigned g_sbits[NIMG * NBOX];                 // packed score bits
__device__ float    g_s[NIMG][KPAD];                      // sorted top scores
__device__ float4   g_box[NIMG][KPAD];                    // gathered boxes
__device__ float    g_y[NIMG][KPAD];                      // gathered targets
__device__ float    g_pt[(size_t)NIMG * NJB * KPAD * 8];  // prune, j-tiled
__device__ float    g_v[NIMG][KPAD];                      // rescored
__device__ float    g_c[NIMG][KPAD];                      // prec*y per i

// ---------------- K1: scores = max over channels 1..84 ----------------
// 2016 blocks x 128 threads; each block handles 128 rows; coalesced float4
// staging through shared, then per-thread row max (stride 85 -> conflict-free).
__global__ __launch_bounds__(128) void k_scores(const float* __restrict__ preds) {
    __shared__ __align__(16) float sh[128 * NCH];
    int img = blockIdx.x / 126;
    int ch  = blockIdx.x % 126;
    size_t base = ((size_t)img * NBOX + (size_t)ch * 128) * NCH;
    const float4* src = reinterpret_cast<const float4*>(preds + base);
    float4* dst = reinterpret_cast<float4*>(sh);
    #pragma unroll 4
    for (int u = threadIdx.x; u < 128 * NCH / 4; u += 128) dst[u] = src[u];
    __syncthreads();
    int r = threadIdx.x;
    float m = sh[r * NCH + 1];
    #pragma unroll
    for (int c = 2; c < NCH; ++c) m = fmaxf(m, sh[r * NCH + c]);
    g_sbits[(size_t)img * NBOX + ch * 128 + r] = __float_as_uint(m);
}

// ---------------- K2: per-image radix select + stable sort + gather ----------------
__global__ __launch_bounds__(512) void k_select(const float4* __restrict__ boxes,
                                                const int* __restrict__ tgt) {
    const int img = blockIdx.x;
    const int tid = threadIdx.x;
    __shared__ unsigned hist[2048];
    __shared__ unsigned gsum[128];
    __shared__ unsigned long long sbuf[1024];
    __shared__ unsigned s_bin, s_rem, s_cnt;
    const unsigned* sb = g_sbits + (size_t)img * NBOX;

    auto zero_hist = [&]() {
        for (int u = tid; u < 2048; u += 512) hist[u] = 0;
        __syncthreads();
    };
    auto agg_add = [&](unsigned bin) {
        unsigned active = __activemask();
        unsigned mask = __match_any_sync(active, bin);
        unsigned leader = __ffs(mask) - 1;
        if ((tid & 31) == leader) atomicAdd(&hist[bin], __popc(mask));
    };
    auto find_bin = [&](unsigned target) {
        __syncthreads();
        if (tid < 128) {
            unsigned ssum = 0;
            #pragma unroll
            for (int u = 0; u < 16; ++u) ssum += hist[2047 - (tid * 16 + u)];
            gsum[tid] = ssum;
        }
        __syncthreads();
        if (tid == 0) {
            unsigned cum = 0; int g = 0;
            for (; g < 127; ++g) { if (cum + gsum[g] >= target) break; cum += gsum[g]; }
            for (int u = 0; u < 16; ++u) {
                int bin = 2047 - (g * 16 + u);
                unsigned c = hist[bin];
                if (cum + c >= target) { s_bin = (unsigned)bin; s_rem = target - cum; break; }
                cum += c;
            }
        }
        __syncthreads();
    };

    // pass 1: top 11 bits
    zero_hist();
    for (int j = tid; j < NBOX; j += 512) agg_add(sb[j] >> 21);
    find_bin(KSEL);
    unsigned b1 = s_bin, r1 = s_rem;
    __syncthreads();

    // pass 2: next 11 bits among bin b1
    zero_hist();
    for (int j = tid; j < NBOX; j += 512) {
        unsigned bits = sb[j];
        if ((bits >> 21) == b1) agg_add((bits >> 10) & 0x7FFu);
    }
    find_bin(r1);
    unsigned b2 = s_bin, r2 = s_rem;
    __syncthreads();

    // pass 3: low 10 bits
    zero_hist();
    unsigned pfx = (b1 << 11) | b2;     // equals bits>>10 of candidates
    for (int j = tid; j < NBOX; j += 512) {
        unsigned bits = sb[j];
        if ((bits >> 10) == pfx) agg_add(bits & 0x3FFu);
    }
    find_bin(r2);
    unsigned T = (pfx << 10) | s_bin;
    __syncthreads();

    // gather all with bits >= T (count = 500 + extra exact ties, <= ~510)
    for (int u = tid; u < 1024; u += 512) sbuf[u] = ~0ULL;
    if (tid == 0) s_cnt = 0;
    __syncthreads();
    for (int j = tid; j < NBOX; j += 512) {
        unsigned bits = sb[j];
        if (bits >= T) {
            unsigned p = atomicAdd(&s_cnt, 1);
            if (p < 1024)
                sbuf[p] = ~(((unsigned long long)bits << 32) |
                            (unsigned long long)(0xFFFFFFFFu - (unsigned)j));
        }
    }
    __syncthreads();

    // bitonic sort ascending on ~key  => descending by (bits, then ascending index)
    for (unsigned kk = 2; kk <= 1024; kk <<= 1) {
        for (unsigned st = kk >> 1; st > 0; st >>= 1) {
            unsigned t = (unsigned)tid;
            unsigned i = ((t & ~(st - 1)) << 1) | (t & (st - 1));
            unsigned j2 = i | st;
            bool up = ((i & kk) == 0);
            unsigned long long a = sbuf[i], b = sbuf[j2];
            if ((a > b) == up) { sbuf[i] = b; sbuf[j2] = a; }
            __syncthreads();
        }
    }

    // emit top 500 (sorted) + zero padding
    if (tid < KSEL) {
        unsigned long long key = ~sbuf[tid];
        unsigned bits = (unsigned)(key >> 32);
        unsigned idx  = 0xFFFFFFFFu - (unsigned)(key & 0xFFFFFFFFull);
        g_s[img][tid] = __uint_as_float(bits);
        g_box[img][tid] = boxes[(size_t)img * NBOX + idx];
        g_y[img][tid] = (float)tgt[(size_t)img * NBOX + idx];
    } else {
        g_s[img][tid] = 0.f;
        g_box[img][tid] = make_float4(0.f, 0.f, 0.f, 0.f);
        g_y[img][tid] = 0.f;
    }
}

// ---------------- K3: precompute prune matrix, j-tiled layout ----------------
// grid (NJB, NIMG) x 512. Layout: g_pt[((img*NJB + jb)*KPAD + i)*8 + t], j = jb*8+t.
__global__ __launch_bounds__(512) void k_prune() {
    const int jb = blockIdx.x, img = blockIdx.y;
    const int i  = threadIdx.x;
    __shared__ float4 bj[8];
    __shared__ float  aj[8];
    if (i < 8) {
        int j = jb * 8 + i;
        float4 b = g_box[img][j < KPAD ? j : 0];
        bj[i] = b;
        aj[i] = fmaxf(b.z - b.x, 0.f) * fmaxf(b.w - b.y, 0.f);
    }
    __syncthreads();
    float4 bi = g_box[img][i];
    float ai = fmaxf(bi.z - bi.x, 0.f) * fmaxf(bi.w - bi.y, 0.f);
    float out[8];
    #pragma unroll
    for (int t = 0; t < 8; ++t) {
        int j = jb * 8 + t;
        float p = 0.f;
        if (i < KSEL && j < i) {
            float4 bb = bj[t];
            float iw = fminf(bi.z, bb.z) - fmaxf(bi.x, bb.x);
            float ih = fminf(bi.w, bb.w) - fmaxf(bi.y, bb.y);
            if (iw > 0.f && ih > 0.f) {
                float inter = iw * ih;
                float uni = ai + aj[t] - inter;
                float iou = inter / fmaxf(uni, 1e-9f);
                p = 1.f / (1.f + __expf((0.4f - iou) * 10.f));
            } else {
                p = SIG_NEG4;   // sigmoid(-4): zero-overlap constant (~98% of pairs)
            }
        }
        out[t] = p;
    }
    float4* dst = reinterpret_cast<float4*>(
        &g_pt[(((size_t)img * NJB + jb) * KPAD + i) * 8]);
    dst[0] = make_float4(out[0], out[1], out[2], out[3]);
    dst[1] = make_float4(out[4], out[5], out[6], out[7]);
}

// ---------------- K4: sequential soft-NMS recursion (column updates) ----------------
__global__ __launch_bounds__(512) void k_nms() {
    const int img = blockIdx.x;
    const int tid = threadIdx.x;
    __shared__ float vsh[KPAD];
    float s = g_s[img][tid];
    float acc = 0.f;
    const float4* base = reinterpret_cast<const float4*>(g_pt) +
                         ((size_t)img * NJB * KPAD + tid) * 2;
    float4 c0 = base[0], c1 = base[1];
    for (int jb = 0; jb < NJB; ++jb) {
        float4 n0 = c0, n1 = c1;
        if (jb < NJB - 1) {                       // prefetch next tile (L2)
            const float4* nb = base + (size_t)(jb + 1) * (KPAD * 2);
            n0 = nb[0]; n1 = nb[1];
        }
        float pc[8] = {c0.x, c0.y, c0.z, c0.w, c1.x, c1.y, c1.z, c1.w};
        int tmax = (jb == NJB - 1) ? 4 : 8;       // 500 = 62*8 + 4
        #pragma unroll 8
        for (int t = 0; t < tmax; ++t) {
            int j = jb * 8 + t;
            if (tid == j) vsh[j] = fminf(fmaxf(s - acc, 0.f), 1.f);
            __syncthreads();
            if (tid > j && tid < KSEL) acc += pc[t] * vsh[j];
        }
        c0 = n0; c1 = n1;
    }
    __syncthreads();
    g_v[img][tid] = (tid < KSEL) ? vsh[tid] : 0.f;
}

// ---------------- K5: ap_loss row sums ----------------
// grid (4, NIMG) x 128. Only rows with y=1 contribute.
__global__ __launch_bounds__(128) void k_ap() {
    const int img = blockIdx.y;
    const int i = blockIdx.x * 128 + threadIdx.x;
    __shared__ float vs[KPAD], ys[KPAD];
    for (int u = threadIdx.x; u < KPAD; u += 128) {
        vs[u] = g_v[img][u];
        ys[u] = g_y[img][u];
    }
    __syncthreads();
    float ci = 0.f;
    if (i < KSEL && ys[i] != 0.f) {
        float vi = vs[i];
        float sh = 0.f, shy = 0.f;
        #pragma unroll 4
        for (int j = 0; j < KSEL; ++j) {
            float h = 1.f / (1.f + __expf((vi - vs[j]) * 20.f));  // sigmoid((vj-vi)/0.05)
            sh += h;
            shy += h * ys[j];
        }
        // remove diagonal term h_ii = 0.5 (y_i = 1 in this branch)
        float rank = 0.5f + sh;      // 1 + (sh - 0.5)
        float pos  = 0.5f + shy;     // 1 + (shy - 0.5*y_i)
        ci = pos / rank;             // * y_i (=1)
    }
    g_c[img][i] = ci;
}

// ---------------- K6: deterministic final reduction ----------------
__global__ __launch_bounds__(512) void k_final(float* __restrict__ out) {
    __shared__ float red[512];
    const int tid = threadIdx.x;
    float lsum = 0.f;
    for (int img = 0; img < NIMG; ++img) {
        red[tid] = g_c[img][tid];
        __syncthreads();
        for (int s = 256; s > 0; s >>= 1) {
            if (tid < s) red[tid] += red[tid + s];
            __syncthreads();
        }
        float sc = red[0];
        __syncthreads();
        red[tid] = g_y[img][tid];
        __syncthreads();
        for (int s = 256; s > 0; s >>= 1) {
            if (tid < s) red[tid] += red[tid + s];
            __syncthreads();
        }
        float sy = red[0];
        __syncthreads();
        if (tid == 0) lsum += 1.f - sc / fmaxf(sy, 1.f);
    }
    if (tid == 0) out[0] = lsum / (float)NIMG;
}

// ---------------- driver ----------------
extern "C" void kernel_launch(void* const* d_in, const int* in_sizes, int n_in,
                              void* d_out, int out_size) {
    const float* preds = nullptr;
    const float* boxes = nullptr;
    const int*   targets = nullptr;
    for (int i = 0; i < n_in; ++i) {
        long sz = in_sizes[i];
        if (sz == (long)NIMG * NBOX * NCH) preds = (const float*)d_in[i];
        else if (sz == (long)NIMG * NBOX * 4) boxes = (const float*)d_in[i];
        else if (sz == (long)NIMG * NBOX) targets = (const int*)d_in[i];
    }
    if (!preds)   preds   = (const float*)d_in[0];
    if (!boxes)   boxes   = (const float*)d_in[1];
    if (!targets) targets = (const int*)d_in[2];

    k_scores<<<NIMG * 126, 128>>>(preds);
    k_select<<<NIMG, 512>>>(reinterpret_cast<const float4*>(boxes), targets);
    k_prune<<<dim3(NJB, NIMG), 512>>>();
    k_nms<<<NIMG, 512>>>();
    k_ap<<<dim3(4, NIMG), 128>>>();
    k_final<<<1, 512>>>((float*)d_out);
}

// round 2
// speedup vs baseline: 1.6303x; 1.6303x over previous
#include <cuda_runtime.h>
#include <cuda_bf16.h>
#include <cstdint>

#define NIMG 16
#define NBOX 16128
#define NCH  85
#define KSEL 500
#define KPAD 512
#define NCB  16            // 512 / 32 column blocks
#define SIG_NEG4 0.017986210f   // sigmoid(-4) for zero-overlap pairs

// ---------------- device scratch (no allocations allowed) ----------------
__device__ unsigned g_sbits[NIMG * NBOX];                 // packed score bits
__device__ float    g_s[NIMG][KPAD];                      // sorted top scores
__device__ float4   g_box[NIMG][KPAD];                    // gathered boxes
__device__ float    g_y[NIMG][KPAD];                      // gathered targets
__device__ float    g_p[(size_t)NIMG * NCB * KPAD * 32];  // prune, [img][cb][i][t]
__device__ float    g_E[NIMG][KPAD];                      // exp(20*v)
__device__ float    g_yE[NIMG][KPAD];                     // y * exp(20*v)
__device__ float    g_c[NIMG][KPAD];                      // prec*y per row

__device__ __forceinline__ float frcp(float x) {
    float r; asm("rcp.approx.f32 %0, %1;" : "=f"(r) : "f"(x)); return r;
}

// ---------------- K1: scores = max over channels 1..84 ----------------
__global__ __launch_bounds__(128) void k_scores(const float* __restrict__ preds) {
    __shared__ __align__(16) float sh[128 * NCH];
    int img = blockIdx.x / 126;
    int ch  = blockIdx.x % 126;
    size_t base = ((size_t)img * NBOX + (size_t)ch * 128) * NCH;
    const float4* src = reinterpret_cast<const float4*>(preds + base);
    float4* dst = reinterpret_cast<float4*>(sh);
    #pragma unroll 8
    for (int u = threadIdx.x; u < 128 * NCH / 4; u += 128) dst[u] = src[u];
    __syncthreads();
    int r = threadIdx.x;
    float m = sh[r * NCH + 1];
    #pragma unroll
    for (int c = 2; c < NCH; ++c) m = fmaxf(m, sh[r * NCH + c]);
    g_sbits[(size_t)img * NBOX + ch * 128 + r] = __float_as_uint(m);
}

// ---------------- K2: per-image radix select (4x8-bit, warp-private hist) ----------------
__global__ __launch_bounds__(512) void k_select(const float4* __restrict__ boxes,
                                                const int* __restrict__ tgt) {
    const int img = blockIdx.x;
    const int tid = threadIdx.x;
    const int w = tid >> 5, lane = tid & 31;
    __shared__ unsigned whist[16 * 256];     // warp-private histograms
    __shared__ unsigned hist[256];
    __shared__ unsigned wtot[16];
    __shared__ unsigned s_bin, s_rem, s_cnt;
    __shared__ unsigned long long sbuf[1024];
    const unsigned* sb = g_sbits + (size_t)img * NBOX;

    unsigned prefix = 0;
    unsigned target = KSEL;

    #pragma unroll
    for (int pass = 0; pass < 4; ++pass) {
        const int shift = 24 - pass * 8;
        for (int u = tid; u < 4096; u += 512) whist[u] = 0;
        __syncthreads();
        for (int j = tid; j < NBOX; j += 512) {
            unsigned bits = sb[j];
            bool ok = (pass == 0) || ((bits >> (shift + 8)) == prefix);
            unsigned act = __ballot_sync(0xFFFFFFFFu, ok);
            if (ok) {
                unsigned bin = (bits >> shift) & 255u;
                unsigned mask = __match_any_sync(act, bin);
                if ((mask & ((1u << lane) - 1u)) == 0)   // leader
                    whist[w * 256 + bin] += __popc(mask);
            }
        }
        __syncthreads();
        if (tid < 256) {
            unsigned h = 0;
            #pragma unroll
            for (int ww = 0; ww < 16; ++ww) h += whist[ww * 256 + tid];
            hist[tid] = h;
        }
        __syncthreads();
        // suffix-sum from top bin: scan position p=tid maps to bin 255-tid
        unsigned x0 = (tid < 256) ? hist[255 - tid] : 0u;
        unsigned x = x0;
        #pragma unroll
        for (int off = 1; off < 32; off <<= 1) {
            unsigned yv = __shfl_up_sync(0xFFFFFFFFu, x, off);
            if (lane >= off) x += yv;
        }
        if (lane == 31) wtot[w] = x;
        __syncthreads();
        unsigned add = 0;
        #pragma unroll
        for (int ww = 0; ww < 8; ++ww) if (ww < w) add += wtot[ww];
        unsigned inc = x + add;
        if (tid < 256 && inc >= target && (inc - x0) < target) {
            s_bin = 255u - (unsigned)tid;
            s_rem = target - (inc - x0);
        }
        __syncthreads();
        prefix = (prefix << 8) | s_bin;
        target = s_rem;
        __syncthreads();
    }
    const unsigned T = prefix;

    // gather all with bits >= T (count = 500 + exact ties)
    for (int u = tid; u < 1024; u += 512) sbuf[u] = ~0ULL;
    if (tid == 0) s_cnt = 0;
    __syncthreads();
    for (int j = tid; j < NBOX; j += 512) {
        unsigned bits = sb[j];
        if (bits >= T) {
            unsigned p = atomicAdd(&s_cnt, 1);
            if (p < 1024)
                sbuf[p] = ~(((unsigned long long)bits << 32) |
                            (unsigned long long)(0xFFFFFFFFu - (unsigned)j));
        }
    }
    __syncthreads();

    // bitonic sort ascending on ~key => descending (bits, then ascending index)
    for (unsigned kk = 2; kk <= 1024; kk <<= 1) {
        for (unsigned st = kk >> 1; st > 0; st >>= 1) {
            unsigned t = (unsigned)tid;
            unsigned i = ((t & ~(st - 1)) << 1) | (t & (st - 1));
            unsigned j2 = i | st;
            bool up = ((i & kk) == 0);
            unsigned long long a = sbuf[i], b = sbuf[j2];
            if ((a > b) == up) { sbuf[i] = b; sbuf[j2] = a; }
            __syncthreads();
        }
    }

    if (tid < KSEL) {
        unsigned long long key = ~sbuf[tid];
        unsigned bits = (unsigned)(key >> 32);
        unsigned idx  = 0xFFFFFFFFu - (unsigned)(key & 0xFFFFFFFFull);
        g_s[img][tid] = __uint_as_float(bits);
        g_box[img][tid] = boxes[(size_t)img * NBOX + idx];
        g_y[img][tid] = (float)tgt[(size_t)img * NBOX + idx];
    } else {
        g_s[img][tid] = 0.f;
        g_box[img][tid] = make_float4(0.f, 0.f, 0.f, 0.f);
        g_y[img][tid] = 0.f;
    }
}

// ---------------- K3: prune matrix, layout [img][cb][i][t] ----------------
__global__ __launch_bounds__(512) void k_prune() {
    const int cb = blockIdx.x, img = blockIdx.y;
    const int i  = threadIdx.x;
    __shared__ float4 bj[32];
    __shared__ float  aj[32];
    if (i < 32) {
        float4 b = g_box[img][cb * 32 + i];
        bj[i] = b;
        aj[i] = fmaxf(b.z - b.x, 0.f) * fmaxf(b.w - b.y, 0.f);
    }
    __syncthreads();
    float4 bi = g_box[img][i];
    float ai = fmaxf(bi.z - bi.x, 0.f) * fmaxf(bi.w - bi.y, 0.f);
    float out[32];
    #pragma unroll
    for (int t = 0; t < 32; ++t) {
        int j = cb * 32 + t;
        float p = 0.f;
        if (i < KSEL && j < i) {
            float4 bb = bj[t];
            float iw = fminf(bi.z, bb.z) - fmaxf(bi.x, bb.x);
            float ih = fminf(bi.w, bb.w) - fmaxf(bi.y, bb.y);
            if (iw > 0.f && ih > 0.f) {
                float inter = iw * ih;
                float uni = ai + aj[t] - inter;
                float iou = __fdividef(inter, fmaxf(uni, 1e-9f));
                p = frcp(1.f + __expf((0.4f - iou) * 10.f));
            } else {
                p = SIG_NEG4;
            }
        }
        out[t] = p;
    }
    float4* dst = reinterpret_cast<float4*>(
        &g_p[(((size_t)img * NCB + cb) * KPAD + i) * 32]);
    #pragma unroll
    for (int u = 0; u < 8; ++u) dst[u] = reinterpret_cast<float4*>(out)[u];
}

// ---------------- K4: soft-NMS — warp-resolved 32-column blocks ----------------
__global__ __launch_bounds__(512) void k_nms() {
    const int img = blockIdx.x;
    const int tid = threadIdx.x;
    const int w = tid >> 5, lane = tid & 31;
    __shared__ __align__(16) float vsh[KPAD];
    float r = g_s[img][tid];                     // r = s - acc
    const float4* pb = reinterpret_cast<const float4*>(g_p) +
                       ((size_t)img * NCB * KPAD + tid) * 8;
    float4 cur[8], nxt[8];
    #pragma unroll
    for (int u = 0; u < 8; ++u) cur[u] = pb[u];

    for (int cb = 0; cb < NCB; ++cb) {
        if (cb < NCB - 1 && w >= cb + 1) {       // prefetch next tile
            const float4* nb = pb + (size_t)(cb + 1) * KPAD * 8;
            #pragma unroll
            for (int u = 0; u < 8; ++u) nxt[u] = nb[u];
        }
        float pc[32];
        #pragma unroll
        for (int u = 0; u < 8; ++u) {
            pc[4*u+0] = cur[u].x; pc[4*u+1] = cur[u].y;
            pc[4*u+2] = cur[u].z; pc[4*u+3] = cur[u].w;
        }
        if (w == cb) {
            // serial resolution of 32 diagonal columns via shfl chain
            #pragma unroll
            for (int m = 0; m < 32; ++m) {
                float vm = __shfl_sync(0xFFFFFFFFu, fmaxf(r, 0.f), m);
                if (lane == m) vsh[tid] = vm;
                if (lane > m) r = fmaf(-pc[m], vm, r);
            }
        }
        __syncthreads();
        if (w > cb) {
            const float4* vv = reinterpret_cast<const float4*>(&vsh[cb * 32]);
            #pragma unroll
            for (int u = 0; u < 8; ++u) {
                float4 v4 = vv[u];
                r = fmaf(-pc[4*u+0], v4.x, r);
                r = fmaf(-pc[4*u+1], v4.y, r);
                r = fmaf(-pc[4*u+2], v4.z, r);
                r = fmaf(-pc[4*u+3], v4.w, r);
            }
        }
        #pragma unroll
        for (int u = 0; u < 8; ++u) cur[u] = nxt[u];
    }
    __syncthreads();
    float v = vsh[tid];
    float E = __expf(20.f * v);
    bool valid = tid < KSEL;
    g_E[img][tid]  = valid ? E : 0.f;
    g_yE[img][tid] = valid ? g_y[img][tid] * E : 0.f;
}

// ---------------- K5: ap_loss with exp factorization ----------------
// h_ij = sigmoid((v_j - v_i)/0.05) = E_j / (E_i + E_j),  E = exp(20 v)
__global__ __launch_bounds__(128) void k_ap() {
    const int img = blockIdx.y;
    const int i = blockIdx.x * 128 + threadIdx.x;
    __shared__ float Es[KPAD], yEs[KPAD];
    for (int u = threadIdx.x; u < KPAD; u += 128) {
        Es[u]  = g_E[img][u];
        yEs[u] = g_yE[img][u];
    }
    __syncthreads();
    float ci = 0.f;
    float yi = g_y[img][i];
    if (i < KSEL && yi != 0.f) {
        float Ei = Es[i];
        float sh = 0.f, shy = 0.f;
        #pragma unroll 4
        for (int j = 0; j < KSEL; ++j) {
            float ej = Es[j];
            float rr = frcp(Ei + ej);
            sh  = fmaf(ej, rr, sh);
            shy = fmaf(yEs[j], rr, shy);
        }
        // diagonal included as ~0.5: rank = 1 + (sh - 0.5), pos = 1 + (shy - 0.5)
        ci = __fdividef(0.5f + shy, 0.5f + sh);
    }
    g_c[img][i] = ci;
}

// ---------------- K6: warp-per-image final reduction ----------------
__global__ __launch_bounds__(512) void k_final(float* __restrict__ out) {
    const int w = threadIdx.x >> 5, lane = threadIdx.x & 31;
    __shared__ float part[16];
    float sc = 0.f, sy = 0.f;
    #pragma unroll
    for (int u = lane; u < KPAD; u += 32) {
        sc += g_c[w][u];
        sy += g_y[w][u];
    }
    #pragma unroll
    for (int off = 16; off > 0; off >>= 1) {
        sc += __shfl_down_sync(0xFFFFFFFFu, sc, off);
        sy += __shfl_down_sync(0xFFFFFFFFu, sy, off);
    }
    if (lane == 0) part[w] = 1.f - sc / fmaxf(sy, 1.f);
    __syncthreads();
    if (threadIdx.x == 0) {
        float t = 0.f;
        #pragma unroll
        for (int k = 0; k < NIMG; ++k) t += part[k];
        out[0] = t / (float)NIMG;
    }
}

// ---------------- driver ----------------
extern "C" void kernel_launch(void* const* d_in, const int* in_sizes, int n_in,
                              void* d_out, int out_size) {
    const float* preds = nullptr;
    const float* boxes = nullptr;
    const int*   targets = nullptr;
    for (int i = 0; i < n_in; ++i) {
        long sz = in_sizes[i];
        if (sz == (long)NIMG * NBOX * NCH) preds = (const float*)d_in[i];
        else if (sz == (long)NIMG * NBOX * 4) boxes = (const float*)d_in[i];
        else if (sz == (long)NIMG * NBOX) targets = (const int*)d_in[i];
    }
    if (!preds)   preds   = (const float*)d_in[0];
    if (!boxes)   boxes   = (const float*)d_in[1];
    if (!targets) targets = (const int*)d_in[2];

    k_scores<<<NIMG * 126, 128>>>(preds);
    k_select<<<NIMG, 512>>>(reinterpret_cast<const float4*>(boxes), targets);
    k_prune<<<dim3(NCB, NIMG), 512>>>();
    k_nms<<<NIMG, 512>>>();
    k_ap<<<dim3(4, NIMG), 128>>>();
    k_final<<<1, 512>>>((float*)d_out);
}